// round 2
// baseline (speedup 1.0000x reference)
#include <cuda_runtime.h>

// Fused spiking conv2d: 3x3 conv (T=128, Cin=16, Cout=64, H=W=64, pad=1) + LIF scan.
// Thread = 2 adjacent-w pixels x 4 couts; membrane state in registers across the
// sequential t loop. Packed fma.rn.f32x2 (2 pixels/instr), (cin,kh,kw) sequential
// fma chain pinned by inline asm to match the reference's im2col k-order.
// Epilogue rounds (conv + b) FIRST, then (state + conv_t), matching the reference.

#define T_STEPS 128
#define CIN     16
#define HH      64
#define WWID    64
#define COUT    64

typedef unsigned long long ull;

__device__ __forceinline__ void fma2(ull& d, ull a, ull b) {
    asm("fma.rn.f32x2 %0, %1, %2, %0;" : "+l"(d) : "l"(a), "l"(b));
}
__device__ __forceinline__ ull pack2(float lo, float hi) {
    ull r;
    asm("mov.b64 %0, {%1, %2};" : "=l"(r) : "f"(lo), "f"(hi));
    return r;
}
__device__ __forceinline__ void unpack2(ull v, float& lo, float& hi) {
    asm("mov.b64 {%0, %1}, %2;" : "=f"(lo), "=f"(hi) : "l"(v));
}
// Plain fp32 add with rounding order pinned (no reassociation possible anyway,
// but keep it explicit and fusion-proof).
__device__ __forceinline__ float fadd(float a, float b) {
    float r;
    asm("add.rn.f32 %0, %1, %2;" : "=f"(r) : "f"(a), "f"(b));
    return r;
}

__global__ __launch_bounds__(256, 1)
void snn_conv_scan_kernel(const float* __restrict__ x,
                          const float* __restrict__ Wg,
                          const float* __restrict__ bg,
                          float* __restrict__ out)
{
    // Duplicated weight pairs: ws[cin][tap][cout_local] = (w, w)
    __shared__ float2 ws[CIN][9][4];

    const int tid    = threadIdx.x;
    const int ty     = tid >> 4;          // 0..15 : h within tile
    const int tx     = tid & 15;          // 0..15 : w-pair within tile
    const int tile_h = blockIdx.x & 3;    // 4 tiles of 16 rows
    const int tile_w = blockIdx.x >> 2;   // 2 tiles of 32 cols
    const int c0     = blockIdx.y << 2;   // 16 groups of 4 couts

    const int h0 = tile_h * 16 + ty;
    const int w0 = tile_w * 32 + tx * 2;

    // Stage duplicated weights (once)
    for (int i = tid; i < CIN * 9 * 4; i += 256) {
        int c   = i & 3;
        int rem = i >> 2;
        int tap = rem % 9;
        int cin = rem / 9;
        float w = Wg[((c0 + c) * CIN + cin) * 9 + tap];
        ws[cin][tap][c] = make_float2(w, w);
    }
    __syncthreads();

    const float bb0 = bg[c0 + 0];
    const float bb1 = bg[c0 + 1];
    const float bb2 = bg[c0 + 2];
    const float bb3 = bg[c0 + 3];

    const bool wm1 = (w0 > 0);      // left halo valid
    const bool wp2 = (w0 < 62);     // right halo valid
    const bool hm1 = (h0 > 0);      // top halo valid
    const bool hp1 = (h0 < 63);     // bottom halo valid

    // Membrane state: s[cout_local][pixel]
    float s00 = 0.f, s01 = 0.f, s10 = 0.f, s11 = 0.f;
    float s20 = 0.f, s21 = 0.f, s30 = 0.f, s31 = 0.f;

    const float* xbase0 = x + h0 * WWID + w0;
    float* obase = out + (size_t)c0 * (HH * WWID) + h0 * WWID + w0;

    #pragma unroll 1
    for (int t = 0; t < T_STEPS; ++t) {
        const float* xb = xbase0 + t * (CIN * HH * WWID);

        ull a0 = 0ull, a1 = 0ull, a2 = 0ull, a3 = 0ull;  // (pix0,pix1) accum per cout

        #pragma unroll
        for (int cin = 0; cin < CIN; ++cin) {
            const float* p = xb + cin * (HH * WWID);
            #pragma unroll
            for (int r = 0; r < 3; ++r) {
                const float* pr = p + (r - 1) * WWID;
                const bool v = (r == 0) ? hm1 : ((r == 2) ? hp1 : true);

                float xm = (v && wm1) ? pr[-1] : 0.f;                       // col w0-1
                ull  pb  = v ? *reinterpret_cast<const ull*>(pr) : 0ull;    // cols w0, w0+1
                float xp = (v && wp2) ? pr[2] : 0.f;                        // col w0+2

                float x1, x2;
                unpack2(pb, x1, x2);
                ull pa = pack2(xm, x1);   // kw = 0 taps for (pix0, pix1)
                ull pc = pack2(x2, xp);   // kw = 2 taps

                // Weight pairs for taps kw=0..2, couts 0..3 (LDS.128 x6)
                const ulonglong2* wv =
                    reinterpret_cast<const ulonglong2*>(&ws[cin][r * 3][0]);
                ulonglong2 wA = wv[0], wA2 = wv[1];  // kw=0: couts {0,1},{2,3}
                ulonglong2 wB = wv[2], wB2 = wv[3];  // kw=1
                ulonglong2 wC = wv[4], wC2 = wv[5];  // kw=2

                fma2(a0, pa, wA.x);  fma2(a1, pa, wA.y);
                fma2(a2, pa, wA2.x); fma2(a3, pa, wA2.y);
                fma2(a0, pb, wB.x);  fma2(a1, pb, wB.y);
                fma2(a2, pb, wB2.x); fma2(a3, pb, wB2.y);
                fma2(a0, pc, wC.x);  fma2(a1, pc, wC.y);
                fma2(a2, pc, wC2.x); fma2(a3, pc, wC2.y);
            }
        }

        // LIF update + spike emission for 4 couts x 2 pixels.
        // Rounding order matches reference: conv_t = conv + b (round), then
        // state = state + conv_t (round).
        float* o = obase + (size_t)t * (COUT * HH * WWID);
        float lo, hi;

        unpack2(a0, lo, hi);
        {
            float c0v = fadd(lo, bb0), c1v = fadd(hi, bb0);
            float v0 = fadd(s00, c0v), v1 = fadd(s01, c1v);
            float k0 = (v0 >= 8.f) ? 1.f : 0.f, k1 = (v1 >= 8.f) ? 1.f : 0.f;
            v0 = (v0 >= 8.f) ? 0.f : v0;       v1 = (v1 >= 8.f) ? 0.f : v1;
            s00 = fmaxf(v0, -1.f);             s01 = fmaxf(v1, -1.f);
            *reinterpret_cast<float2*>(o + 0 * (HH * WWID)) = make_float2(k0, k1);
        }
        unpack2(a1, lo, hi);
        {
            float c0v = fadd(lo, bb1), c1v = fadd(hi, bb1);
            float v0 = fadd(s10, c0v), v1 = fadd(s11, c1v);
            float k0 = (v0 >= 8.f) ? 1.f : 0.f, k1 = (v1 >= 8.f) ? 1.f : 0.f;
            v0 = (v0 >= 8.f) ? 0.f : v0;       v1 = (v1 >= 8.f) ? 0.f : v1;
            s10 = fmaxf(v0, -1.f);             s11 = fmaxf(v1, -1.f);
            *reinterpret_cast<float2*>(o + 1 * (HH * WWID)) = make_float2(k0, k1);
        }
        unpack2(a2, lo, hi);
        {
            float c0v = fadd(lo, bb2), c1v = fadd(hi, bb2);
            float v0 = fadd(s20, c0v), v1 = fadd(s21, c1v);
            float k0 = (v0 >= 8.f) ? 1.f : 0.f, k1 = (v1 >= 8.f) ? 1.f : 0.f;
            v0 = (v0 >= 8.f) ? 0.f : v0;       v1 = (v1 >= 8.f) ? 0.f : v1;
            s20 = fmaxf(v0, -1.f);             s21 = fmaxf(v1, -1.f);
            *reinterpret_cast<float2*>(o + 2 * (HH * WWID)) = make_float2(k0, k1);
        }
        unpack2(a3, lo, hi);
        {
            float c0v = fadd(lo, bb3), c1v = fadd(hi, bb3);
            float v0 = fadd(s30, c0v), v1 = fadd(s31, c1v);
            float k0 = (v0 >= 8.f) ? 1.f : 0.f, k1 = (v1 >= 8.f) ? 1.f : 0.f;
            v0 = (v0 >= 8.f) ? 0.f : v0;       v1 = (v1 >= 8.f) ? 0.f : v1;
            s30 = fmaxf(v0, -1.f);             s31 = fmaxf(v1, -1.f);
            *reinterpret_cast<float2*>(o + 3 * (HH * WWID)) = make_float2(k0, k1);
        }
    }
}

extern "C" void kernel_launch(void* const* d_in, const int* in_sizes, int n_in,
                              void* d_out, int out_size)
{
    const float* x  = (const float*)d_in[0];   // [128,16,64,64]
    const float* Wg = (const float*)d_in[1];   // [64,16,3,3]
    const float* bg = (const float*)d_in[2];   // [64]
    float* out      = (float*)d_out;           // [128,64,64,64]

    dim3 grid(8, 16);   // 8 spatial tiles (4h x 2w) x 16 cout groups
    snn_conv_scan_kernel<<<grid, 256>>>(x, Wg, bg, out);
}

// round 3
// speedup vs baseline: 1.4681x; 1.4681x over previous
#include <cuda_runtime.h>

// Fused spiking conv2d (T=128, Cin=16, Cout=64, 64x64, pad=1) + LIF scan.
// Thread = 2 adjacent-w pixels x 4 couts, membrane state in registers across t.
// x tile staged into smem per timestep via cp.async (double-buffered, prefetch
// t+1 during compute of t); halos zero-initialized once so the inner loop has
// no boundary predicates. Packed fma.rn.f32x2, exact (cin,kh,kw) order and
// (conv+b) then (state+conv) rounding — bitwise-identical to the reference.

#define T_STEPS 128
#define CIN     16
#define HH      64
#define WWID    64
#define COUT    64

#define ROWS_S  18              // 16 rows + top/bottom halo
#define COLS_S  40              // fetch span w0tile-4 .. w0tile+35 (16B aligned)
#define BUF_FLOATS (CIN * ROWS_S * COLS_S)   // 11520 floats per buffer
#define CHUNKS_PER_T (CIN * ROWS_S * 10)     // 2880 float4 chunks
#define STAGE_ITERS 12                        // ceil(2880/256)

typedef unsigned long long ull;

__device__ __forceinline__ void fma2(ull& d, ull a, ull b) {
    asm("fma.rn.f32x2 %0, %1, %2, %0;" : "+l"(d) : "l"(a), "l"(b));
}
__device__ __forceinline__ ull pack2(float lo, float hi) {
    ull r;
    asm("mov.b64 %0, {%1, %2};" : "=l"(r) : "f"(lo), "f"(hi));
    return r;
}
__device__ __forceinline__ void unpack2(ull v, float& lo, float& hi) {
    asm("mov.b64 {%0, %1}, %2;" : "=f"(lo), "=f"(hi) : "l"(v));
}
__device__ __forceinline__ float fadd(float a, float b) {
    float r;
    asm("add.rn.f32 %0, %1, %2;" : "=f"(r) : "f"(a), "f"(b));
    return r;
}
__device__ __forceinline__ void cp16(unsigned saddr, const void* g) {
    asm volatile("cp.async.cg.shared.global [%0], [%1], 16;"
                 :: "r"(saddr), "l"(g));
}
__device__ __forceinline__ void cp_commit() {
    asm volatile("cp.async.commit_group;");
}
__device__ __forceinline__ void cp_wait0() {
    asm volatile("cp.async.wait_group 0;");
}

__global__ __launch_bounds__(256, 1)
void snn_conv_scan_kernel(const float* __restrict__ x,
                          const float* __restrict__ Wg,
                          const float* __restrict__ bg,
                          float* __restrict__ out)
{
    extern __shared__ float xs[];                 // 2 * BUF_FLOATS
    __shared__ float2 ws[CIN][9][4];              // duplicated weight pairs

    const int tid    = threadIdx.x;
    const int ty     = tid >> 4;          // 0..15 : h within tile
    const int tx     = tid & 15;          // 0..15 : w-pair within tile
    const int tile_h = blockIdx.x & 3;    // 4 tiles of 16 rows
    const int tile_w = blockIdx.x >> 2;   // 2 tiles of 32 cols
    const int c0     = blockIdx.y << 2;   // 16 groups of 4 couts

    const int ht = tile_h * 16;
    const int wt = tile_w * 32;
    const int h0 = ht + ty;
    const int w0 = wt + tx * 2;

    // ---- stage duplicated weights (once) ----
    for (int i = tid; i < CIN * 9 * 4; i += 256) {
        int c   = i & 3;
        int rem = i >> 2;
        int tap = rem % 9;
        int cin = rem / 9;
        float w = Wg[((c0 + c) * CIN + cin) * 9 + tap];
        ws[cin][tap][c] = make_float2(w, w);
    }

    // ---- zero both x buffers (halos must read as 0.0f forever) ----
    {
        float4* z = reinterpret_cast<float4*>(xs);
        for (int i = tid; i < 2 * BUF_FLOATS / 4; i += 256)
            z[i] = make_float4(0.f, 0.f, 0.f, 0.f);
    }
    __syncthreads();

    // ---- precompute per-thread stage descriptors (valid/goff/soff), reused every t ----
    unsigned xs_u32;
    {
        unsigned long long tmp = __cvta_generic_to_shared(xs);
        xs_u32 = (unsigned)tmp;
    }
    int  goff[STAGE_ITERS];     // byte offset into x's t-slice
    int  soff[STAGE_ITERS];     // byte offset into smem buffer
    bool vld[STAGE_ITERS];
    #pragma unroll
    for (int j = 0; j < STAGE_ITERS; ++j) {
        int i = tid + 256 * j;
        int cin = i / 180;
        int rem = i - cin * 180;
        int rr  = rem / 10;
        int k   = rem - rr * 10;
        int gh  = ht - 1 + rr;
        int gc  = wt - 4 + 4 * k;
        bool ok = (i < CHUNKS_PER_T) && (gh >= 0) && (gh < HH) &&
                  (gc >= 0) && (gc + 3 < WWID);
        vld[j]  = ok;
        goff[j] = (cin * (HH * WWID) + gh * WWID + gc) * 4;
        soff[j] = ((cin * ROWS_S + rr) * COLS_S + 4 * k) * 4;
    }

    const float bb0 = bg[c0 + 0];
    const float bb1 = bg[c0 + 1];
    const float bb2 = bg[c0 + 2];
    const float bb3 = bg[c0 + 3];

    // membrane state: s[cout_local][pixel]
    float s00 = 0.f, s01 = 0.f, s10 = 0.f, s11 = 0.f;
    float s20 = 0.f, s21 = 0.f, s30 = 0.f, s31 = 0.f;

    float* obase = out + (size_t)c0 * (HH * WWID) + h0 * WWID + w0;

    // ---- prologue: stage t = 0 into buffer 0 ----
    {
        const char* src = (const char*)x;   // t = 0 slice
        unsigned sb = xs_u32;
        #pragma unroll
        for (int j = 0; j < STAGE_ITERS; ++j)
            if (vld[j]) cp16(sb + soff[j], src + goff[j]);
        cp_commit();
        cp_wait0();
    }
    __syncthreads();

    #pragma unroll 1
    for (int t = 0; t < T_STEPS; ++t) {
        // kick prefetch of t+1 into the other buffer
        if (t + 1 < T_STEPS) {
            const char* src = (const char*)(x + (size_t)(t + 1) * (CIN * HH * WWID));
            unsigned sb = xs_u32 + ((t + 1) & 1) * (BUF_FLOATS * 4);
            #pragma unroll
            for (int j = 0; j < STAGE_ITERS; ++j)
                if (vld[j]) cp16(sb + soff[j], src + goff[j]);
            cp_commit();
        }

        // compute conv for t from current buffer (all LDS, no boundary checks)
        const float* cur = xs + (t & 1) * BUF_FLOATS;
        ull a0 = 0ull, a1 = 0ull, a2 = 0ull, a3 = 0ull;

        #pragma unroll
        for (int cin = 0; cin < CIN; ++cin) {
            #pragma unroll
            for (int r = 0; r < 3; ++r) {
                const float* rowp = cur + (cin * ROWS_S + ty + r) * COLS_S + 2 * tx;
                float xm = rowp[3];                                   // col w0-1
                ull  pb  = *reinterpret_cast<const ull*>(rowp + 4);   // cols w0, w0+1
                float xp = rowp[6];                                   // col w0+2

                float x1, x2;
                unpack2(pb, x1, x2);
                ull pa = pack2(xm, x1);   // kw = 0 taps
                ull pc = pack2(x2, xp);   // kw = 2 taps

                const ulonglong2* wv =
                    reinterpret_cast<const ulonglong2*>(&ws[cin][r * 3][0]);
                ulonglong2 wA = wv[0], wA2 = wv[1];  // kw=0: couts {0,1},{2,3}
                ulonglong2 wB = wv[2], wB2 = wv[3];  // kw=1
                ulonglong2 wC = wv[4], wC2 = wv[5];  // kw=2

                fma2(a0, pa, wA.x);  fma2(a1, pa, wA.y);
                fma2(a2, pa, wA2.x); fma2(a3, pa, wA2.y);
                fma2(a0, pb, wB.x);  fma2(a1, pb, wB.y);
                fma2(a2, pb, wB2.x); fma2(a3, pb, wB2.y);
                fma2(a0, pc, wC.x);  fma2(a1, pc, wC.y);
                fma2(a2, pc, wC2.x); fma2(a3, pc, wC2.y);
            }
        }

        // LIF update + spike emission; rounding order matches reference:
        // conv_t = conv + b (round), then state = state + conv_t (round).
        float* o = obase + (size_t)t * (COUT * HH * WWID);
        float lo, hi;

        unpack2(a0, lo, hi);
        {
            float cA = fadd(lo, bb0), cB = fadd(hi, bb0);
            float v0 = fadd(s00, cA), v1 = fadd(s01, cB);
            float k0 = (v0 >= 8.f) ? 1.f : 0.f, k1 = (v1 >= 8.f) ? 1.f : 0.f;
            v0 = (v0 >= 8.f) ? 0.f : v0;       v1 = (v1 >= 8.f) ? 0.f : v1;
            s00 = fmaxf(v0, -1.f);             s01 = fmaxf(v1, -1.f);
            *reinterpret_cast<float2*>(o + 0 * (HH * WWID)) = make_float2(k0, k1);
        }
        unpack2(a1, lo, hi);
        {
            float cA = fadd(lo, bb1), cB = fadd(hi, bb1);
            float v0 = fadd(s10, cA), v1 = fadd(s11, cB);
            float k0 = (v0 >= 8.f) ? 1.f : 0.f, k1 = (v1 >= 8.f) ? 1.f : 0.f;
            v0 = (v0 >= 8.f) ? 0.f : v0;       v1 = (v1 >= 8.f) ? 0.f : v1;
            s10 = fmaxf(v0, -1.f);             s11 = fmaxf(v1, -1.f);
            *reinterpret_cast<float2*>(o + 1 * (HH * WWID)) = make_float2(k0, k1);
        }
        unpack2(a2, lo, hi);
        {
            float cA = fadd(lo, bb2), cB = fadd(hi, bb2);
            float v0 = fadd(s20, cA), v1 = fadd(s21, cB);
            float k0 = (v0 >= 8.f) ? 1.f : 0.f, k1 = (v1 >= 8.f) ? 1.f : 0.f;
            v0 = (v0 >= 8.f) ? 0.f : v0;       v1 = (v1 >= 8.f) ? 0.f : v1;
            s20 = fmaxf(v0, -1.f);             s21 = fmaxf(v1, -1.f);
            *reinterpret_cast<float2*>(o + 2 * (HH * WWID)) = make_float2(k0, k1);
        }
        unpack2(a3, lo, hi);
        {
            float cA = fadd(lo, bb3), cB = fadd(hi, bb3);
            float v0 = fadd(s30, cA), v1 = fadd(s31, cB);
            float k0 = (v0 >= 8.f) ? 1.f : 0.f, k1 = (v1 >= 8.f) ? 1.f : 0.f;
            v0 = (v0 >= 8.f) ? 0.f : v0;       v1 = (v1 >= 8.f) ? 0.f : v1;
            s30 = fmaxf(v0, -1.f);             s31 = fmaxf(v1, -1.f);
            *reinterpret_cast<float2*>(o + 3 * (HH * WWID)) = make_float2(k0, k1);
        }

        // drain the t+1 prefetch, then make the buffer swap safe
        if (t + 1 < T_STEPS) cp_wait0();
        __syncthreads();
    }
}

extern "C" void kernel_launch(void* const* d_in, const int* in_sizes, int n_in,
                              void* d_out, int out_size)
{
    const float* x  = (const float*)d_in[0];   // [128,16,64,64]
    const float* Wg = (const float*)d_in[1];   // [64,16,3,3]
    const float* bg = (const float*)d_in[2];   // [64]
    float* out      = (float*)d_out;           // [128,64,64,64]

    static int attr_set = 0;
    size_t xs_bytes = (size_t)2 * BUF_FLOATS * sizeof(float);   // 92160 B
    if (!attr_set) {
        cudaFuncSetAttribute(snn_conv_scan_kernel,
                             cudaFuncAttributeMaxDynamicSharedMemorySize,
                             (int)xs_bytes);
        attr_set = 1;
    }

    dim3 grid(8, 16);   // 8 spatial tiles (4h x 2w) x 16 cout groups
    snn_conv_scan_kernel<<<grid, 256, xs_bytes>>>(x, Wg, bg, out);
}